// round 14
// baseline (speedup 1.0000x reference)
#include <cuda_runtime.h>
#include <cuda_fp16.h>
#include <cstdint>

#define NSEQ 4096
#define CDIM 256
#define HEADS 8
#define DDIM 64
#define HD   512
#define LDQ  72   // fp16 smem leading dim (144B stride -> conflict-free ldmatrix)
#define KVPARTS 4
#define NTP  (NSEQ / 64 / KVPARTS)   // 16 kv tiles per part

// Scratch (static device arrays; no allocation allowed)
__device__ __half g_qh[NSEQ * HD];
__device__ __half g_kh[NSEQ * HD];
__device__ __half g_vh[NSEQ * HD];
__device__ float  g_g [NSEQ * HD];
__device__ __half g_oh[NSEQ * HD];
__device__ float  g_opart[KVPARTS][NSEQ * HD];      // unnormalized O partials
__device__ float  g_ls[KVPARTS][HEADS * NSEQ];      // row-sum partials
// f16 copies of inputs/weights (pre-converted once)
__device__ __half g_xq[NSEQ * CDIM];
__device__ __half g_xk[NSEQ * CDIM];
__device__ __half g_xv[NSEQ * CDIM];
__device__ __half g_wq[HD * CDIM];
__device__ __half g_wk[HD * CDIM];
__device__ __half g_wv[HD * CDIM];
__device__ __half g_wg[HD * CDIM];
__device__ __half g_wo[CDIM * HD];

// ---------------------------------------------------------------------------
// PTX helpers
// ---------------------------------------------------------------------------
__device__ __forceinline__ uint32_t smaddr(const void* p) {
    return (uint32_t)__cvta_generic_to_shared(p);
}

__device__ __forceinline__ void ldsm_x4(uint32_t& r0, uint32_t& r1, uint32_t& r2, uint32_t& r3,
                                        uint32_t addr) {
    asm volatile("ldmatrix.sync.aligned.m8n8.x4.shared.b16 {%0,%1,%2,%3}, [%4];"
                 : "=r"(r0), "=r"(r1), "=r"(r2), "=r"(r3) : "r"(addr));
}

__device__ __forceinline__ void ldsm_x4_t(uint32_t& r0, uint32_t& r1, uint32_t& r2, uint32_t& r3,
                                          uint32_t addr) {
    asm volatile("ldmatrix.sync.aligned.m8n8.x4.trans.shared.b16 {%0,%1,%2,%3}, [%4];"
                 : "=r"(r0), "=r"(r1), "=r"(r2), "=r"(r3) : "r"(addr));
}

// f32-accumulate variant (PV + projection GEMMs)
__device__ __forceinline__ void mma16816(float* d, const uint32_t* a, uint32_t b0, uint32_t b1) {
    asm volatile(
        "mma.sync.aligned.m16n8k16.row.col.f32.f16.f16.f32 "
        "{%0,%1,%2,%3}, {%4,%5,%6,%7}, {%8,%9}, {%0,%1,%2,%3};"
        : "+f"(d[0]), "+f"(d[1]), "+f"(d[2]), "+f"(d[3])
        : "r"(a[0]), "r"(a[1]), "r"(a[2]), "r"(a[3]), "r"(b0), "r"(b1));
}

// f16-accumulate variant (QK^T only; bias added later in f32)
__device__ __forceinline__ void mma16816_h(uint32_t* d, const uint32_t* a, uint32_t b0, uint32_t b1) {
    asm volatile(
        "mma.sync.aligned.m16n8k16.row.col.f16.f16.f16.f16 "
        "{%0,%1}, {%2,%3,%4,%5}, {%6,%7}, {%0,%1};"
        : "+r"(d[0]), "+r"(d[1])
        : "r"(a[0]), "r"(a[1]), "r"(a[2]), "r"(a[3]), "r"(b0), "r"(b1));
}

// Pack two fp32 into f16x2: result = {lo=x, hi=y}
__device__ __forceinline__ uint32_t pack_f16x2(float x, float y) {
    uint32_t r;
    asm("{\n\t.reg .b16 lo, hi;\n\t"
        "cvt.rn.f16.f32 lo, %1;\n\t"
        "cvt.rn.f16.f32 hi, %2;\n\t"
        "mov.b32 %0, {lo, hi};\n\t}"
        : "=r"(r) : "f"(x), "f"(y));
    return r;
}

__device__ __forceinline__ void cp_async16(uint32_t dst, const void* src) {
    asm volatile("cp.async.cg.shared.global [%0], [%1], 16;" :: "r"(dst), "l"(src));
}
__device__ __forceinline__ void cp_commit() {
    asm volatile("cp.async.commit_group;");
}
template <int N>
__device__ __forceinline__ void cp_wait() {
    asm volatile("cp.async.wait_group %0;" :: "n"(N));
}

// ---------------------------------------------------------------------------
// Convert inputs + weights to f16 (once). 3,801,088 elems, 4 per thread.
// ---------------------------------------------------------------------------
__global__ void __launch_bounds__(256) convert_f16(const float* __restrict__ q_x,
                                                   const float* __restrict__ k_x,
                                                   const float* __restrict__ v_x,
                                                   const float* __restrict__ wq,
                                                   const float* __restrict__ wk,
                                                   const float* __restrict__ wv,
                                                   const float* __restrict__ wg,
                                                   const float* __restrict__ wo) {
    const size_t i = ((size_t)blockIdx.x * 256 + threadIdx.x) * 4;
    const float* src;
    __half* dst;
    size_t off;
    if (i < 3145728) {                       // activations: 3 x 2^20
        const int seg = (int)(i >> 20);
        off = i & 1048575;
        src = (seg == 0) ? q_x : (seg == 1) ? k_x : v_x;
        dst = (seg == 0) ? g_xq : (seg == 1) ? g_xk : g_xv;
    } else {                                 // weights: 5 x 2^17
        const size_t w = i - 3145728;
        const int seg = (int)(w >> 17);
        off = w & 131071;
        src = (seg == 0) ? wq : (seg == 1) ? wk : (seg == 2) ? wv : (seg == 3) ? wg : wo;
        dst = (seg == 0) ? g_wq : (seg == 1) ? g_wk : (seg == 2) ? g_wv : (seg == 3) ? g_wg : g_wo;
    }
    float4 v = *(const float4*)(src + off);
    uint2 p;
    p.x = pack_f16x2(v.x, v.y);
    p.y = pack_f16x2(v.z, v.w);
    *(uint2*)(dst + off) = p;
}

// ---------------------------------------------------------------------------
// Merged projection GEMMs (pure f16, cp.async double-buffered):
// blockIdx.z in {0:q, 1:k, 2:v, 3:gate}
// C[m, n] = sum_c A[m, c] * B[n, c], tile M=128 x N=64, K-chunks of 64.
// ---------------------------------------------------------------------------
__global__ void __launch_bounds__(256) proj_all(const float* __restrict__ bg) {
    extern __shared__ __half psm[];
    __half* As = psm;                        // [2][128][LDQ]
    __half* Bs = psm + 2 * 128 * LDQ;        // [2][64][LDQ]

    const int z = blockIdx.z;
    const __half* A = (z == 1) ? g_xk : (z == 2) ? g_xv : g_xq;
    const __half* B = (z == 0) ? g_wq : (z == 1) ? g_wk : (z == 2) ? g_wv : g_wg;

    const int m0 = blockIdx.y * 128, n0 = blockIdx.x * 64;
    const int tid = threadIdx.x;
    const int warp = tid >> 5;
    const int lane = tid & 31;
    const int g = lane >> 2, t = lane & 3;

    const int a_row = 16 * warp + (lane & 15);
    const int a_ch  = (lane >> 4) * 8;
    const int b_row = ((lane >> 4) & 1) * 8 + (lane & 7);
    const int b_ch  = ((lane >> 3) & 1) * 8;

    // cp.async: A 4x16B/thread (2 threads/row), B 2x16B/thread (4 threads/row)
    const int arow = tid >> 1, ac = (tid & 1) * 32;
    const int brow = tid >> 2, bc = (tid & 3) * 16;

    float acc[8][4] = {};

    // Prologue: chunk 0
    {
        uint32_t ad = smaddr(As + arow * LDQ + ac);
        const __half* ap = A + (size_t)(m0 + arow) * CDIM + ac;
#pragma unroll
        for (int c = 0; c < 4; c++) cp_async16(ad + 16 * c, ap + 8 * c);
        uint32_t bd = smaddr(Bs + brow * LDQ + bc);
        const __half* bp = B + (size_t)(n0 + brow) * CDIM + bc;
        cp_async16(bd, bp);  cp_async16(bd + 16, bp + 8);
        cp_commit();
    }

    for (int ch = 0; ch < 4; ch++) {
        const int buf = ch & 1;
        __half* Ab = As + buf * 128 * LDQ;
        __half* Bb = Bs + buf * 64 * LDQ;

        __syncthreads();
        if (ch + 1 < 4) {
            const int k0n = (ch + 1) * 64;
            uint32_t ad = smaddr(As + (buf ^ 1) * 128 * LDQ + arow * LDQ + ac);
            const __half* ap = A + (size_t)(m0 + arow) * CDIM + k0n + ac;
#pragma unroll
            for (int c = 0; c < 4; c++) cp_async16(ad + 16 * c, ap + 8 * c);
            uint32_t bd = smaddr(Bs + (buf ^ 1) * 64 * LDQ + brow * LDQ + bc);
            const __half* bp = B + (size_t)(n0 + brow) * CDIM + k0n + bc;
            cp_async16(bd, bp);  cp_async16(bd + 16, bp + 8);
        }
        cp_commit();
        cp_wait<1>();
        __syncthreads();

#pragma unroll
        for (int kk = 0; kk < 4; kk++) {
            uint32_t qa[4];
            ldsm_x4(qa[0], qa[1], qa[2], qa[3],
                    smaddr(Ab + a_row * LDQ + 16 * kk + a_ch));
#pragma unroll
            for (int jp = 0; jp < 4; jp++) {
                uint32_t b0, b1, b2, b3;
                ldsm_x4(b0, b1, b2, b3,
                        smaddr(Bb + (16 * jp + b_row) * LDQ + 16 * kk + b_ch));
                mma16816(acc[2 * jp],     qa, b0, b1);
                mma16816(acc[2 * jp + 1], qa, b2, b3);
            }
        }
    }

#pragma unroll
    for (int r = 0; r < 2; r++) {
#pragma unroll
        for (int j = 0; j < 8; j++) {
            const int row = m0 + 16 * warp + g + 8 * r;
            const int col = n0 + 8 * j + 2 * t;
            float x = acc[j][2 * r], y = acc[j][2 * r + 1];
            if (z == 0) {
                *(uint32_t*)(g_qh + (size_t)row * HD + col) = pack_f16x2(x * 0.125f, y * 0.125f);
            } else if (z == 1) {
                *(uint32_t*)(g_kh + (size_t)row * HD + col) = pack_f16x2(x, y);
            } else if (z == 2) {
                *(uint32_t*)(g_vh + (size_t)row * HD + col) = pack_f16x2(x, y);
            } else {
                float2 bv = *(const float2*)(bg + col);
                float2 ov;
                ov.x = 1.0f / (1.0f + __expf(-(x + bv.x)));
                ov.y = 1.0f / (1.0f + __expf(-(y + bv.y)));
                *(float2*)(g_g + (size_t)row * HD + col) = ov;
            }
        }
    }
}

// ---------------------------------------------------------------------------
// Output GEMM (pure f16, cp.async): out[m,n] = sum_j g_oh[m,j]*g_wo[n,j] + bo[n]
// ---------------------------------------------------------------------------
__global__ void __launch_bounds__(256) out_gemm(const float* __restrict__ bvec,
                                                float* __restrict__ outp) {
    extern __shared__ __half psm[];
    __half* As = psm;                        // [2][128][LDQ]
    __half* Bs = psm + 2 * 128 * LDQ;        // [2][64][LDQ]

    const int m0 = blockIdx.y * 128, n0 = blockIdx.x * 64;
    const int tid = threadIdx.x;
    const int warp = tid >> 5;
    const int lane = tid & 31;
    const int g = lane >> 2, t = lane & 3;

    const int a_row = 16 * warp + (lane & 15);
    const int a_ch  = (lane >> 4) * 8;
    const int b_row = ((lane >> 4) & 1) * 8 + (lane & 7);
    const int b_ch  = ((lane >> 3) & 1) * 8;

    const int arow = tid >> 1, ac = (tid & 1) * 32;
    const int brow = tid >> 2, bc = (tid & 3) * 16;

    float acc[8][4] = {};

    // Prologue: chunk 0
    {
        uint32_t ad = smaddr(As + arow * LDQ + ac);
        const __half* ap = g_oh + (size_t)(m0 + arow) * HD + ac;
#pragma unroll
        for (int c = 0; c < 4; c++) cp_async16(ad + 16 * c, ap + 8 * c);
        uint32_t bd = smaddr(Bs + brow * LDQ + bc);
        const __half* bp = g_wo + (size_t)(n0 + brow) * HD + bc;
        cp_async16(bd, bp);  cp_async16(bd + 16, bp + 8);
        cp_commit();
    }

    for (int ch = 0; ch < 8; ch++) {
        const int buf = ch & 1;
        __half* Ab = As + buf * 128 * LDQ;
        __half* Bb = Bs + buf * 64 * LDQ;

        __syncthreads();
        if (ch + 1 < 8) {
            const int k0n = (ch + 1) * 64;
            uint32_t ad = smaddr(As + (buf ^ 1) * 128 * LDQ + arow * LDQ + ac);
            const __half* ap = g_oh + (size_t)(m0 + arow) * HD + k0n + ac;
#pragma unroll
            for (int c = 0; c < 4; c++) cp_async16(ad + 16 * c, ap + 8 * c);
            uint32_t bd = smaddr(Bs + (buf ^ 1) * 64 * LDQ + brow * LDQ + bc);
            const __half* bp = g_wo + (size_t)(n0 + brow) * HD + k0n + bc;
            cp_async16(bd, bp);  cp_async16(bd + 16, bp + 8);
        }
        cp_commit();
        cp_wait<1>();
        __syncthreads();

#pragma unroll
        for (int kk = 0; kk < 4; kk++) {
            uint32_t qa[4];
            ldsm_x4(qa[0], qa[1], qa[2], qa[3],
                    smaddr(Ab + a_row * LDQ + 16 * kk + a_ch));
#pragma unroll
            for (int jp = 0; jp < 4; jp++) {
                uint32_t b0, b1, b2, b3;
                ldsm_x4(b0, b1, b2, b3,
                        smaddr(Bb + (16 * jp + b_row) * LDQ + 16 * kk + b_ch));
                mma16816(acc[2 * jp],     qa, b0, b1);
                mma16816(acc[2 * jp + 1], qa, b2, b3);
            }
        }
    }

#pragma unroll
    for (int r = 0; r < 2; r++) {
#pragma unroll
        for (int j = 0; j < 8; j++) {
            const int row = m0 + 16 * warp + g + 8 * r;
            const int col = n0 + 8 * j + 2 * t;
            float2 bv = *(const float2*)(bvec + col);
            float2 ov;
            ov.x = acc[j][2 * r]     + bv.x;
            ov.y = acc[j][2 * r + 1] + bv.y;
            *(float2*)(outp + (size_t)row * CDIM + col) = ov;
        }
    }
}

// ---------------------------------------------------------------------------
// Split-KV flash attention (unchanged from round 12's winning config).
// ---------------------------------------------------------------------------
__global__ void __launch_bounds__(256, 2) attn_kernel(const float* __restrict__ bias) {
    extern __shared__ __half sm[];
    __half* Qs = sm;                         // [128][LDQ]
    __half* Ks = Qs + 128 * LDQ;             // [2][64][LDQ]
    __half* Vs = Ks + 2 * 64 * LDQ;          // [2][64][LDQ]

    const int h    = blockIdx.y;
    const int q0   = blockIdx.x * 128;
    const int part = blockIdx.z;
    const int kvb  = part * (NSEQ / KVPARTS);

    const int tid = threadIdx.x;
    const int warp = tid >> 5;
    const int lane = tid & 31;
    const int g  = lane >> 2;
    const int t  = lane & 3;

    for (int u = tid; u < 1024; u += 256) {
        const int row = u >> 3;
        const int c8  = (u & 7) * 8;
        *(uint4*)(Qs + row * LDQ + c8) =
            *(const uint4*)(g_qh + (size_t)(q0 + row) * HD + h * DDIM + c8);
    }

    float o[8][4];
#pragma unroll
    for (int j = 0; j < 8; j++)
#pragma unroll
        for (int e = 0; e < 4; e++) o[j][e] = 0.0f;
    float lrun[2] = {0.0f, 0.0f};

    const int a_row = 16 * warp + (lane & 15);
    const int a_ch  = (lane >> 4) * 8;
    const int b_row = ((lane >> 4) & 1) * 8 + (lane & 7);
    const int b_ch  = ((lane >> 3) & 1) * 8;
    const int v_row = ((lane >> 3) & 1) * 8 + (lane & 7);
    const int v_ch  = ((lane >> 4) & 1) * 8;

    const int cp_row = tid >> 2;
    const int cp_c8  = (tid & 3) * 16;

    // Prologue: K/V tile 0 of this part
    {
        const __half* kp = g_kh + (size_t)(kvb + cp_row) * HD + h * DDIM + cp_c8;
        const __half* vp = g_vh + (size_t)(kvb + cp_row) * HD + h * DDIM + cp_c8;
        uint32_t kd = smaddr(Ks + cp_row * LDQ + cp_c8);
        uint32_t vd = smaddr(Vs + cp_row * LDQ + cp_c8);
        cp_async16(kd, kp);           cp_async16(kd + 16, kp + 8);
        cp_async16(vd, vp);           cp_async16(vd + 16, vp + 8);
        cp_commit();
    }

    // Hoist Q fragments
    __syncthreads();
    uint32_t qa[4][4];
#pragma unroll
    for (int kk = 0; kk < 4; kk++)
        ldsm_x4(qa[kk][0], qa[kk][1], qa[kk][2], qa[kk][3],
                smaddr(Qs + a_row * LDQ + 16 * kk + a_ch));

    const float* bias_base = bias + (size_t)(q0 + 16 * warp + g) * NSEQ;

    for (int kt = 0; kt < NTP; kt++) {
        const int buf = kt & 1;
        __half* Kb = Ks + buf * 64 * LDQ;
        __half* Vb = Vs + buf * 64 * LDQ;

        __syncthreads();

        if (kt + 1 < NTP) {
            const int k0n = kvb + (kt + 1) * 64;
            const __half* kp = g_kh + (size_t)(k0n + cp_row) * HD + h * DDIM + cp_c8;
            const __half* vp = g_vh + (size_t)(k0n + cp_row) * HD + h * DDIM + cp_c8;
            uint32_t kd = smaddr(Ks + (buf ^ 1) * 64 * LDQ + cp_row * LDQ + cp_c8);
            uint32_t vd = smaddr(Vs + (buf ^ 1) * 64 * LDQ + cp_row * LDQ + cp_c8);
            cp_async16(kd, kp);       cp_async16(kd + 16, kp + 8);
            cp_async16(vd, vp);       cp_async16(vd + 16, vp + 8);
        }
        cp_commit();

        const int k0 = kvb + kt * 64;
        float2 bb0[8], bb1[8];
#pragma unroll
        for (int j = 0; j < 8; j++) {
            const int col = k0 + 8 * j + 2 * t;
            bb0[j] = *(const float2*)(bias_base + col);
            bb1[j] = *(const float2*)(bias_base + (size_t)8 * NSEQ + col);
        }

        cp_wait<1>();
        __syncthreads();

        uint32_t sf[8][2];
#pragma unroll
        for (int j = 0; j < 8; j++) { sf[j][0] = 0u; sf[j][1] = 0u; }

#pragma unroll
        for (int kk = 0; kk < 4; kk++) {
#pragma unroll
            for (int jp = 0; jp < 4; jp++) {
                uint32_t b0, b1, b2, b3;
                ldsm_x4(b0, b1, b2, b3,
                        smaddr(Kb + (16 * jp + b_row) * LDQ + 16 * kk + b_ch));
                mma16816_h(sf[2 * jp],     qa[kk], b0, b1);
                mma16816_h(sf[2 * jp + 1], qa[kk], b2, b3);
            }
        }

        uint32_t pa[4][4];
#pragma unroll
        for (int j = 0; j < 8; j++) {
            float2 lo = __half22float2(*(const __half2*)&sf[j][0]);
            float2 hi = __half22float2(*(const __half2*)&sf[j][1]);
            const float p00 = __expf(lo.x + bb0[j].x);
            const float p01 = __expf(lo.y + bb0[j].y);
            const float p10 = __expf(hi.x + bb1[j].x);
            const float p11 = __expf(hi.y + bb1[j].y);
            lrun[0] += p00 + p01;
            lrun[1] += p10 + p11;
            const int m = j >> 1;
            const int hl = j & 1;
            pa[m][2 * hl]     = pack_f16x2(p00, p01);
            pa[m][2 * hl + 1] = pack_f16x2(p10, p11);
        }

#pragma unroll
        for (int m = 0; m < 4; m++) {
#pragma unroll
            for (int jp = 0; jp < 4; jp++) {
                uint32_t b0, b1, b2, b3;
                ldsm_x4_t(b0, b1, b2, b3,
                          smaddr(Vb + (16 * m + v_row) * LDQ + 16 * jp + v_ch));
                mma16816(o[2 * jp],     pa[m], b0, b1);
                mma16816(o[2 * jp + 1], pa[m], b2, b3);
            }
        }
    }

#pragma unroll
    for (int r = 0; r < 2; r++) {
        lrun[r] += __shfl_xor_sync(0xffffffffu, lrun[r], 1);
        lrun[r] += __shfl_xor_sync(0xffffffffu, lrun[r], 2);
    }

    float* opart = g_opart[part];
#pragma unroll
    for (int r = 0; r < 2; r++) {
        const int row = q0 + 16 * warp + g + 8 * r;
        if (t == 0)
            g_ls[part][h * NSEQ + row] = lrun[r];
        const size_t rb = (size_t)row * HD + h * DDIM;
#pragma unroll
        for (int j = 0; j < 8; j++) {
            const int col = 8 * j + 2 * t;
            float2 ov;
            ov.x = o[j][2 * r];
            ov.y = o[j][2 * r + 1];
            *(float2*)(opart + rb + col) = ov;
        }
    }
}

// ---------------------------------------------------------------------------
// Combine: sum the 4 kv-part partials, normalize, gate, store fp16 g_oh.
// ---------------------------------------------------------------------------
__global__ void __launch_bounds__(256) combine_kernel() {
    const size_t idx = ((size_t)blockIdx.x * 256 + threadIdx.x) * 4;
    const int row = (int)(idx / HD);
    const int col = (int)(idx % HD);
    const int h   = col / DDIM;

    float4 s = *(const float4*)(g_opart[0] + idx);
    float4 s1 = *(const float4*)(g_opart[1] + idx);
    float4 s2 = *(const float4*)(g_opart[2] + idx);
    float4 s3 = *(const float4*)(g_opart[3] + idx);
    s.x += s1.x + s2.x + s3.x;
    s.y += s1.y + s2.y + s3.y;
    s.z += s1.z + s2.z + s3.z;
    s.w += s1.w + s2.w + s3.w;

    const int li = h * NSEQ + row;
    const float l = g_ls[0][li] + g_ls[1][li] + g_ls[2][li] + g_ls[3][li];
    const float inv = 1.0f / l;

    float4 gv = *(const float4*)(g_g + idx);
    uint2 p;
    p.x = pack_f16x2(s.x * inv * gv.x, s.y * inv * gv.y);
    p.y = pack_f16x2(s.z * inv * gv.z, s.w * inv * gv.w);
    *(uint2*)(g_oh + idx) = p;
}

// ---------------------------------------------------------------------------
extern "C" void kernel_launch(void* const* d_in, const int* in_sizes, int n_in,
                              void* d_out, int out_size) {
    const float* q_x  = (const float*)d_in[0];
    const float* k_x  = (const float*)d_in[1];
    const float* v_x  = (const float*)d_in[2];
    const float* bias = (const float*)d_in[3];
    const float* wq   = (const float*)d_in[4];
    const float* wk   = (const float*)d_in[5];
    const float* wv   = (const float*)d_in[6];
    const float* wg   = (const float*)d_in[7];
    const float* bg   = (const float*)d_in[8];
    const float* wo   = (const float*)d_in[9];
    const float* bo   = (const float*)d_in[10];
    float* out = (float*)d_out;

    // f16 pre-conversion of activations + weights (3,801,088 elems / 1024)
    convert_f16<<<3712, 256>>>(q_x, k_x, v_x, wq, wk, wv, wg, wo);

    const size_t gsmem = (size_t)(2 * 128 + 2 * 64) * LDQ * sizeof(__half);  // 55296 B
    cudaFuncSetAttribute(proj_all, cudaFuncAttributeMaxDynamicSharedMemorySize, (int)gsmem);
    proj_all<<<dim3(HD / 64, NSEQ / 128, 4), 256, gsmem>>>(bg);

    const size_t smem = (size_t)(128 + 4 * 64) * LDQ * sizeof(__half);  // 55296 B
    cudaFuncSetAttribute(attn_kernel, cudaFuncAttributeMaxDynamicSharedMemorySize, (int)smem);
    attn_kernel<<<dim3(NSEQ / 128, HEADS, KVPARTS), 256, smem>>>(bias);

    combine_kernel<<<(NSEQ * HD) / 1024, 256>>>();

    cudaFuncSetAttribute(out_gemm, cudaFuncAttributeMaxDynamicSharedMemorySize, (int)gsmem);
    out_gemm<<<dim3(CDIM / 64, NSEQ / 128), 256, gsmem>>>(bo, out);
}

// round 15
// speedup vs baseline: 1.0109x; 1.0109x over previous
#include <cuda_runtime.h>
#include <cuda_fp16.h>
#include <cstdint>

#define NSEQ 4096
#define CDIM 256
#define HEADS 8
#define DDIM 64
#define HD   512
#define LDQ  72   // fp16 smem leading dim (144B stride -> conflict-free ldmatrix)
#define KVPARTS 8
#define NTP  (NSEQ / 64 / KVPARTS)   // 8 kv tiles per part

// Scratch (static device arrays; no allocation allowed)
__device__ __half g_qh[NSEQ * HD];
__device__ __half g_kh[NSEQ * HD];
__device__ __half g_vh[NSEQ * HD];
__device__ float  g_g [NSEQ * HD];
__device__ __half g_oh[NSEQ * HD];
__device__ __half g_opart[KVPARTS][NSEQ * HD];      // unnormalized O partials (f16)
__device__ float  g_ls[KVPARTS][HEADS * NSEQ];      // row-sum partials

// ---------------------------------------------------------------------------
// PTX helpers
// ---------------------------------------------------------------------------
__device__ __forceinline__ uint32_t smaddr(const void* p) {
    return (uint32_t)__cvta_generic_to_shared(p);
}

__device__ __forceinline__ void ldsm_x4(uint32_t& r0, uint32_t& r1, uint32_t& r2, uint32_t& r3,
                                        uint32_t addr) {
    asm volatile("ldmatrix.sync.aligned.m8n8.x4.shared.b16 {%0,%1,%2,%3}, [%4];"
                 : "=r"(r0), "=r"(r1), "=r"(r2), "=r"(r3) : "r"(addr));
}

__device__ __forceinline__ void ldsm_x4_t(uint32_t& r0, uint32_t& r1, uint32_t& r2, uint32_t& r3,
                                          uint32_t addr) {
    asm volatile("ldmatrix.sync.aligned.m8n8.x4.trans.shared.b16 {%0,%1,%2,%3}, [%4];"
                 : "=r"(r0), "=r"(r1), "=r"(r2), "=r"(r3) : "r"(addr));
}

// f32-accumulate variant (PV + projection GEMMs)
__device__ __forceinline__ void mma16816(float* d, const uint32_t* a, uint32_t b0, uint32_t b1) {
    asm volatile(
        "mma.sync.aligned.m16n8k16.row.col.f32.f16.f16.f32 "
        "{%0,%1,%2,%3}, {%4,%5,%6,%7}, {%8,%9}, {%0,%1,%2,%3};"
        : "+f"(d[0]), "+f"(d[1]), "+f"(d[2]), "+f"(d[3])
        : "r"(a[0]), "r"(a[1]), "r"(a[2]), "r"(a[3]), "r"(b0), "r"(b1));
}

// f16-accumulate variant (QK^T only; bias added later in f32)
__device__ __forceinline__ void mma16816_h(uint32_t* d, const uint32_t* a, uint32_t b0, uint32_t b1) {
    asm volatile(
        "mma.sync.aligned.m16n8k16.row.col.f16.f16.f16.f16 "
        "{%0,%1}, {%2,%3,%4,%5}, {%6,%7}, {%0,%1};"
        : "+r"(d[0]), "+r"(d[1])
        : "r"(a[0]), "r"(a[1]), "r"(a[2]), "r"(a[3]), "r"(b0), "r"(b1));
}

// Pack two fp32 into f16x2: result = {lo=x, hi=y}
__device__ __forceinline__ uint32_t pack_f16x2(float x, float y) {
    uint32_t r;
    asm("{\n\t.reg .b16 lo, hi;\n\t"
        "cvt.rn.f16.f32 lo, %1;\n\t"
        "cvt.rn.f16.f32 hi, %2;\n\t"
        "mov.b32 %0, {lo, hi};\n\t}"
        : "=r"(r) : "f"(x), "f"(y));
    return r;
}

__device__ __forceinline__ void cp_async16(uint32_t dst, const void* src) {
    asm volatile("cp.async.cg.shared.global [%0], [%1], 16;" :: "r"(dst), "l"(src));
}
__device__ __forceinline__ void cp_commit() {
    asm volatile("cp.async.commit_group;");
}
template <int N>
__device__ __forceinline__ void cp_wait() {
    asm volatile("cp.async.wait_group %0;" :: "n"(N));
}

// ---------------------------------------------------------------------------
// Merged projection GEMMs: one launch, blockIdx.z in {0:q, 1:k, 2:v, 3:gate}
// C[m, n] = sum_c X[m, c] * W[n, c], tile M=128 x N=64, K-chunks of 64.
// Software-pipelined: LDGs for chunk k+1 in flight during mma of chunk k.
// ---------------------------------------------------------------------------
__global__ void __launch_bounds__(256) proj_all(const float* __restrict__ q_x,
                                                const float* __restrict__ k_x,
                                                const float* __restrict__ v_x,
                                                const float* __restrict__ wq,
                                                const float* __restrict__ wk,
                                                const float* __restrict__ wv,
                                                const float* __restrict__ wg,
                                                const float* __restrict__ bg) {
    __shared__ __half As[128 * LDQ];
    __shared__ __half Bs[64 * LDQ];

    const int z = blockIdx.z;
    const float* A = (z == 1) ? k_x : (z == 2) ? v_x : q_x;
    const float* B = (z == 0) ? wq : (z == 1) ? wk : (z == 2) ? wv : wg;

    const int m0 = blockIdx.y * 128, n0 = blockIdx.x * 64;
    const int tid = threadIdx.x;
    const int warp = tid >> 5;
    const int lane = tid & 31;
    const int g = lane >> 2, t = lane & 3;

    const int a_row = 16 * warp + (lane & 15);
    const int a_ch  = (lane >> 4) * 8;
    const int b_row = ((lane >> 4) & 1) * 8 + (lane & 7);
    const int b_ch  = ((lane >> 3) & 1) * 8;

    const int srow = tid >> 4;
    const int sc4  = (tid & 15) * 4;

    float acc[8][4] = {};
    float4 ar[8], br[4];

#pragma unroll
    for (int i = 0; i < 8; i++)
        ar[i] = *(const float4*)(A + (size_t)(m0 + srow + 16 * i) * CDIM + sc4);
#pragma unroll
    for (int i = 0; i < 4; i++)
        br[i] = *(const float4*)(B + (size_t)(n0 + srow + 16 * i) * CDIM + sc4);

    for (int k0 = 0; k0 < CDIM; k0 += 64) {
#pragma unroll
        for (int i = 0; i < 8; i++) {
            uint2 p;
            p.x = pack_f16x2(ar[i].x, ar[i].y);
            p.y = pack_f16x2(ar[i].z, ar[i].w);
            *(uint2*)(As + (srow + 16 * i) * LDQ + sc4) = p;
        }
#pragma unroll
        for (int i = 0; i < 4; i++) {
            uint2 p;
            p.x = pack_f16x2(br[i].x, br[i].y);
            p.y = pack_f16x2(br[i].z, br[i].w);
            *(uint2*)(Bs + (srow + 16 * i) * LDQ + sc4) = p;
        }
        __syncthreads();

        if (k0 + 64 < CDIM) {
#pragma unroll
            for (int i = 0; i < 8; i++)
                ar[i] = *(const float4*)(A + (size_t)(m0 + srow + 16 * i) * CDIM + k0 + 64 + sc4);
#pragma unroll
            for (int i = 0; i < 4; i++)
                br[i] = *(const float4*)(B + (size_t)(n0 + srow + 16 * i) * CDIM + k0 + 64 + sc4);
        }

#pragma unroll
        for (int kk = 0; kk < 4; kk++) {
            uint32_t qa[4];
            ldsm_x4(qa[0], qa[1], qa[2], qa[3],
                    smaddr(As + a_row * LDQ + 16 * kk + a_ch));
#pragma unroll
            for (int jp = 0; jp < 4; jp++) {
                uint32_t b0, b1, b2, b3;
                ldsm_x4(b0, b1, b2, b3,
                        smaddr(Bs + (16 * jp + b_row) * LDQ + 16 * kk + b_ch));
                mma16816(acc[2 * jp],     qa, b0, b1);
                mma16816(acc[2 * jp + 1], qa, b2, b3);
            }
        }
        __syncthreads();
    }

#pragma unroll
    for (int r = 0; r < 2; r++) {
#pragma unroll
        for (int j = 0; j < 8; j++) {
            const int row = m0 + 16 * warp + g + 8 * r;
            const int col = n0 + 8 * j + 2 * t;
            float x = acc[j][2 * r], y = acc[j][2 * r + 1];
            if (z == 0) {
                *(uint32_t*)(g_qh + (size_t)row * HD + col) = pack_f16x2(x * 0.125f, y * 0.125f);
            } else if (z == 1) {
                *(uint32_t*)(g_kh + (size_t)row * HD + col) = pack_f16x2(x, y);
            } else if (z == 2) {
                *(uint32_t*)(g_vh + (size_t)row * HD + col) = pack_f16x2(x, y);
            } else {
                float2 bv = *(const float2*)(bg + col);
                float2 ov;
                ov.x = 1.0f / (1.0f + __expf(-(x + bv.x)));
                ov.y = 1.0f / (1.0f + __expf(-(y + bv.y)));
                *(float2*)(g_g + (size_t)row * HD + col) = ov;
            }
        }
    }
}

// ---------------------------------------------------------------------------
// Output GEMM: out[m, n] = sum_j g_oh[m, j] * wo[n, j] + bo[n]   (A fp16)
// Register-staged pipeline over 8 K-chunks (A uint4 raw, B fp32->f16).
// ---------------------------------------------------------------------------
__global__ void __launch_bounds__(256) out_gemm(const float* __restrict__ W,
                                                const float* __restrict__ bvec,
                                                float* __restrict__ outp) {
    __shared__ __half As[128 * LDQ];
    __shared__ __half Bs[64 * LDQ];

    const int m0 = blockIdx.y * 128, n0 = blockIdx.x * 64;
    const int tid = threadIdx.x;
    const int warp = tid >> 5;
    const int lane = tid & 31;
    const int g = lane >> 2, t = lane & 3;

    const int a_row = 16 * warp + (lane & 15);
    const int a_ch  = (lane >> 4) * 8;
    const int b_row = ((lane >> 4) & 1) * 8 + (lane & 7);
    const int b_ch  = ((lane >> 3) & 1) * 8;

    const int arow_s = tid >> 3;
    const int ac8    = (tid & 7) * 8;
    const int brow_s = tid >> 4;
    const int bc4    = (tid & 15) * 4;

    float acc[8][4] = {};
    uint4  ar[4];
    float4 br[4];

#pragma unroll
    for (int i = 0; i < 4; i++)
        ar[i] = *(const uint4*)(g_oh + (size_t)(m0 + arow_s + 32 * i) * HD + ac8);
#pragma unroll
    for (int i = 0; i < 4; i++)
        br[i] = *(const float4*)(W + (size_t)(n0 + brow_s + 16 * i) * HD + bc4);

    for (int k0 = 0; k0 < HD; k0 += 64) {
#pragma unroll
        for (int i = 0; i < 4; i++)
            *(uint4*)(As + (arow_s + 32 * i) * LDQ + ac8) = ar[i];
#pragma unroll
        for (int i = 0; i < 4; i++) {
            uint2 p;
            p.x = pack_f16x2(br[i].x, br[i].y);
            p.y = pack_f16x2(br[i].z, br[i].w);
            *(uint2*)(Bs + (brow_s + 16 * i) * LDQ + bc4) = p;
        }
        __syncthreads();

        if (k0 + 64 < HD) {
#pragma unroll
            for (int i = 0; i < 4; i++)
                ar[i] = *(const uint4*)(g_oh + (size_t)(m0 + arow_s + 32 * i) * HD + k0 + 64 + ac8);
#pragma unroll
            for (int i = 0; i < 4; i++)
                br[i] = *(const float4*)(W + (size_t)(n0 + brow_s + 16 * i) * HD + k0 + 64 + bc4);
        }

#pragma unroll
        for (int kk = 0; kk < 4; kk++) {
            uint32_t qa[4];
            ldsm_x4(qa[0], qa[1], qa[2], qa[3],
                    smaddr(As + a_row * LDQ + 16 * kk + a_ch));
#pragma unroll
            for (int jp = 0; jp < 4; jp++) {
                uint32_t b0, b1, b2, b3;
                ldsm_x4(b0, b1, b2, b3,
                        smaddr(Bs + (16 * jp + b_row) * LDQ + 16 * kk + b_ch));
                mma16816(acc[2 * jp],     qa, b0, b1);
                mma16816(acc[2 * jp + 1], qa, b2, b3);
            }
        }
        __syncthreads();
    }

#pragma unroll
    for (int r = 0; r < 2; r++) {
#pragma unroll
        for (int j = 0; j < 8; j++) {
            const int row = m0 + 16 * warp + g + 8 * r;
            const int col = n0 + 8 * j + 2 * t;
            float2 bv = *(const float2*)(bvec + col);
            float2 ov;
            ov.x = acc[j][2 * r]     + bv.x;
            ov.y = acc[j][2 * r + 1] + bv.y;
            *(float2*)(outp + (size_t)row * CDIM + col) = ov;
        }
    }
}

// ---------------------------------------------------------------------------
// Split-KV flash attention. Grid (32 q-tiles, 8 heads, 8 kv-parts) = 2048
// equal blocks. No-max softmax is linear over kv, so partials (O_unnorm f16,
// rowsum f32) just add in the combine kernel. QK f16-accum, PV f32-accum,
// fp32 bias + softmax. Q fragments hoisted.
// ---------------------------------------------------------------------------
__global__ void __launch_bounds__(256, 2) attn_kernel(const float* __restrict__ bias) {
    extern __shared__ __half sm[];
    __half* Qs = sm;                         // [128][LDQ]
    __half* Ks = Qs + 128 * LDQ;             // [2][64][LDQ]
    __half* Vs = Ks + 2 * 64 * LDQ;          // [2][64][LDQ]

    const int h    = blockIdx.y;
    const int q0   = blockIdx.x * 128;
    const int part = blockIdx.z;
    const int kvb  = part * (NSEQ / KVPARTS);

    const int tid = threadIdx.x;
    const int warp = tid >> 5;
    const int lane = tid & 31;
    const int g  = lane >> 2;
    const int t  = lane & 3;

    for (int u = tid; u < 1024; u += 256) {
        const int row = u >> 3;
        const int c8  = (u & 7) * 8;
        *(uint4*)(Qs + row * LDQ + c8) =
            *(const uint4*)(g_qh + (size_t)(q0 + row) * HD + h * DDIM + c8);
    }

    float o[8][4];
#pragma unroll
    for (int j = 0; j < 8; j++)
#pragma unroll
        for (int e = 0; e < 4; e++) o[j][e] = 0.0f;
    float lrun[2] = {0.0f, 0.0f};

    const int a_row = 16 * warp + (lane & 15);
    const int a_ch  = (lane >> 4) * 8;
    const int b_row = ((lane >> 4) & 1) * 8 + (lane & 7);
    const int b_ch  = ((lane >> 3) & 1) * 8;
    const int v_row = ((lane >> 3) & 1) * 8 + (lane & 7);
    const int v_ch  = ((lane >> 4) & 1) * 8;

    const int cp_row = tid >> 2;
    const int cp_c8  = (tid & 3) * 16;

    // Prologue: K/V tile 0 of this part
    {
        const __half* kp = g_kh + (size_t)(kvb + cp_row) * HD + h * DDIM + cp_c8;
        const __half* vp = g_vh + (size_t)(kvb + cp_row) * HD + h * DDIM + cp_c8;
        uint32_t kd = smaddr(Ks + cp_row * LDQ + cp_c8);
        uint32_t vd = smaddr(Vs + cp_row * LDQ + cp_c8);
        cp_async16(kd, kp);           cp_async16(kd + 16, kp + 8);
        cp_async16(vd, vp);           cp_async16(vd + 16, vp + 8);
        cp_commit();
    }

    // Hoist Q fragments (Qs stable once loaded)
    __syncthreads();
    uint32_t qa[4][4];
#pragma unroll
    for (int kk = 0; kk < 4; kk++)
        ldsm_x4(qa[kk][0], qa[kk][1], qa[kk][2], qa[kk][3],
                smaddr(Qs + a_row * LDQ + 16 * kk + a_ch));

    const float* bias_base = bias + (size_t)(q0 + 16 * warp + g) * NSEQ;

    for (int kt = 0; kt < NTP; kt++) {
        const int buf = kt & 1;
        __half* Kb = Ks + buf * 64 * LDQ;
        __half* Vb = Vs + buf * 64 * LDQ;

        __syncthreads();

        // Prefetch tile kt+1
        if (kt + 1 < NTP) {
            const int k0n = kvb + (kt + 1) * 64;
            const __half* kp = g_kh + (size_t)(k0n + cp_row) * HD + h * DDIM + cp_c8;
            const __half* vp = g_vh + (size_t)(k0n + cp_row) * HD + h * DDIM + cp_c8;
            uint32_t kd = smaddr(Ks + (buf ^ 1) * 64 * LDQ + cp_row * LDQ + cp_c8);
            uint32_t vd = smaddr(Vs + (buf ^ 1) * 64 * LDQ + cp_row * LDQ + cp_c8);
            cp_async16(kd, kp);       cp_async16(kd + 16, kp + 8);
            cp_async16(vd, vp);       cp_async16(vd + 16, vp + 8);
        }
        cp_commit();

        // Bias loads for tile kt (fp32; LDGs in flight during wait + mma)
        const int k0 = kvb + kt * 64;
        float2 bb0[8], bb1[8];
#pragma unroll
        for (int j = 0; j < 8; j++) {
            const int col = k0 + 8 * j + 2 * t;
            bb0[j] = *(const float2*)(bias_base + col);
            bb1[j] = *(const float2*)(bias_base + (size_t)8 * NSEQ + col);
        }

        cp_wait<1>();
        __syncthreads();

        // S = Q K^T  (f16 accumulate, zero-init)
        uint32_t sf[8][2];
#pragma unroll
        for (int j = 0; j < 8; j++) { sf[j][0] = 0u; sf[j][1] = 0u; }

#pragma unroll
        for (int kk = 0; kk < 4; kk++) {
#pragma unroll
            for (int jp = 0; jp < 4; jp++) {
                uint32_t b0, b1, b2, b3;
                ldsm_x4(b0, b1, b2, b3,
                        smaddr(Kb + (16 * jp + b_row) * LDQ + 16 * kk + b_ch));
                mma16816_h(sf[2 * jp],     qa[kk], b0, b1);
                mma16816_h(sf[2 * jp + 1], qa[kk], b2, b3);
            }
        }

        // Softmax without max-subtraction; pack P into A-fragments
        uint32_t pa[4][4];
#pragma unroll
        for (int j = 0; j < 8; j++) {
            float2 lo = __half22float2(*(const __half2*)&sf[j][0]);
            float2 hi = __half22float2(*(const __half2*)&sf[j][1]);
            const float p00 = __expf(lo.x + bb0[j].x);
            const float p01 = __expf(lo.y + bb0[j].y);
            const float p10 = __expf(hi.x + bb1[j].x);
            const float p11 = __expf(hi.y + bb1[j].y);
            lrun[0] += p00 + p01;
            lrun[1] += p10 + p11;
            const int m = j >> 1;
            const int hl = j & 1;
            pa[m][2 * hl]     = pack_f16x2(p00, p01);
            pa[m][2 * hl + 1] = pack_f16x2(p10, p11);
        }

        // O += P V (f32 accumulate)
#pragma unroll
        for (int m = 0; m < 4; m++) {
#pragma unroll
            for (int jp = 0; jp < 4; jp++) {
                uint32_t b0, b1, b2, b3;
                ldsm_x4_t(b0, b1, b2, b3,
                          smaddr(Vb + (16 * m + v_row) * LDQ + 16 * jp + v_ch));
                mma16816(o[2 * jp],     pa[m], b0, b1);
                mma16816(o[2 * jp + 1], pa[m], b2, b3);
            }
        }
    }

    // Reduce row sums across the 4 t-lanes
#pragma unroll
    for (int r = 0; r < 2; r++) {
        lrun[r] += __shfl_xor_sync(0xffffffffu, lrun[r], 1);
        lrun[r] += __shfl_xor_sync(0xffffffffu, lrun[r], 2);
    }

    // Epilogue: write unnormalized f16 partials + row sums for this part
    __half* opart = g_opart[part];
#pragma unroll
    for (int r = 0; r < 2; r++) {
        const int row = q0 + 16 * warp + g + 8 * r;
        if (t == 0)
            g_ls[part][h * NSEQ + row] = lrun[r];
        const size_t rb = (size_t)row * HD + h * DDIM;
#pragma unroll
        for (int j = 0; j < 8; j++) {
            const int col = 8 * j + 2 * t;
            *(uint32_t*)(opart + rb + col) = pack_f16x2(o[j][2 * r], o[j][2 * r + 1]);
        }
    }
}

// ---------------------------------------------------------------------------
// Combine: sum the 8 f16 kv-part partials, normalize, gate, store fp16 g_oh.
// ---------------------------------------------------------------------------
__global__ void __launch_bounds__(256) combine_kernel() {
    const size_t idx = ((size_t)blockIdx.x * 256 + threadIdx.x) * 4;
    const int row = (int)(idx / HD);
    const int col = (int)(idx % HD);
    const int h   = col / DDIM;

    float sx = 0.0f, sy = 0.0f, sz = 0.0f, sw = 0.0f;
#pragma unroll
    for (int p = 0; p < KVPARTS; p++) {
        uint2 raw = *(const uint2*)(g_opart[p] + idx);
        float2 a = __half22float2(*(const __half2*)&raw.x);
        float2 b = __half22float2(*(const __half2*)&raw.y);
        sx += a.x; sy += a.y; sz += b.x; sw += b.y;
    }

    const int li = h * NSEQ + row;
    float l = 0.0f;
#pragma unroll
    for (int p = 0; p < KVPARTS; p++) l += g_ls[p][li];
    const float inv = 1.0f / l;

    float4 gv = *(const float4*)(g_g + idx);
    uint2 pk;
    pk.x = pack_f16x2(sx * inv * gv.x, sy * inv * gv.y);
    pk.y = pack_f16x2(sz * inv * gv.z, sw * inv * gv.w);
    *(uint2*)(g_oh + idx) = pk;
}

// ---------------------------------------------------------------------------
extern "C" void kernel_launch(void* const* d_in, const int* in_sizes, int n_in,
                              void* d_out, int out_size) {
    const float* q_x  = (const float*)d_in[0];
    const float* k_x  = (const float*)d_in[1];
    const float* v_x  = (const float*)d_in[2];
    const float* bias = (const float*)d_in[3];
    const float* wq   = (const float*)d_in[4];
    const float* wk   = (const float*)d_in[5];
    const float* wv   = (const float*)d_in[6];
    const float* wg   = (const float*)d_in[7];
    const float* bg   = (const float*)d_in[8];
    const float* wo   = (const float*)d_in[9];
    const float* bo   = (const float*)d_in[10];
    float* out = (float*)d_out;

    proj_all<<<dim3(HD / 64, NSEQ / 128, 4), 256>>>(q_x, k_x, v_x, wq, wk, wv, wg, bg);

    const size_t smem = (size_t)(128 + 4 * 64) * LDQ * sizeof(__half);  // 55296 B
    cudaFuncSetAttribute(attn_kernel, cudaFuncAttributeMaxDynamicSharedMemorySize, (int)smem);
    attn_kernel<<<dim3(NSEQ / 128, HEADS, KVPARTS), 256, smem>>>(bias);

    combine_kernel<<<(NSEQ * HD) / 1024, 256>>>();

    out_gemm<<<dim3(CDIM / 64, NSEQ / 128), 256>>>(wo, bo, out);
}

// round 16
// speedup vs baseline: 1.0413x; 1.0301x over previous
#include <cuda_runtime.h>
#include <cuda_fp16.h>
#include <cstdint>

#define NSEQ 4096
#define CDIM 256
#define HEADS 8
#define DDIM 64
#define HD   512
#define LDQ  72   // fp16 smem leading dim (144B stride -> conflict-free ldmatrix)
#define KVPARTS 4
#define NTP  (NSEQ / 64 / KVPARTS)   // 16 kv tiles per part

// Scratch (static device arrays; no allocation allowed)
__device__ __half g_qh[NSEQ * HD];
__device__ __half g_kh[NSEQ * HD];
__device__ __half g_vh[NSEQ * HD];
__device__ float  g_g [NSEQ * HD];
__device__ __half g_oh[NSEQ * HD];
__device__ __half g_opart[KVPARTS][NSEQ * HD];      // unnormalized O partials (f16)
__device__ float  g_ls[KVPARTS][HEADS * NSEQ];      // row-sum partials

// ---------------------------------------------------------------------------
// PTX helpers
// ---------------------------------------------------------------------------
__device__ __forceinline__ uint32_t smaddr(const void* p) {
    return (uint32_t)__cvta_generic_to_shared(p);
}

__device__ __forceinline__ void ldsm_x4(uint32_t& r0, uint32_t& r1, uint32_t& r2, uint32_t& r3,
                                        uint32_t addr) {
    asm volatile("ldmatrix.sync.aligned.m8n8.x4.shared.b16 {%0,%1,%2,%3}, [%4];"
                 : "=r"(r0), "=r"(r1), "=r"(r2), "=r"(r3) : "r"(addr));
}

__device__ __forceinline__ void ldsm_x4_t(uint32_t& r0, uint32_t& r1, uint32_t& r2, uint32_t& r3,
                                          uint32_t addr) {
    asm volatile("ldmatrix.sync.aligned.m8n8.x4.trans.shared.b16 {%0,%1,%2,%3}, [%4];"
                 : "=r"(r0), "=r"(r1), "=r"(r2), "=r"(r3) : "r"(addr));
}

// f32-accumulate variant (PV + projection GEMMs)
__device__ __forceinline__ void mma16816(float* d, const uint32_t* a, uint32_t b0, uint32_t b1) {
    asm volatile(
        "mma.sync.aligned.m16n8k16.row.col.f32.f16.f16.f32 "
        "{%0,%1,%2,%3}, {%4,%5,%6,%7}, {%8,%9}, {%0,%1,%2,%3};"
        : "+f"(d[0]), "+f"(d[1]), "+f"(d[2]), "+f"(d[3])
        : "r"(a[0]), "r"(a[1]), "r"(a[2]), "r"(a[3]), "r"(b0), "r"(b1));
}

// f16-accumulate variant (QK^T only; bias added later in f32)
__device__ __forceinline__ void mma16816_h(uint32_t* d, const uint32_t* a, uint32_t b0, uint32_t b1) {
    asm volatile(
        "mma.sync.aligned.m16n8k16.row.col.f16.f16.f16.f16 "
        "{%0,%1}, {%2,%3,%4,%5}, {%6,%7}, {%0,%1};"
        : "+r"(d[0]), "+r"(d[1])
        : "r"(a[0]), "r"(a[1]), "r"(a[2]), "r"(a[3]), "r"(b0), "r"(b1));
}

// Pack two fp32 into f16x2: result = {lo=x, hi=y}
__device__ __forceinline__ uint32_t pack_f16x2(float x, float y) {
    uint32_t r;
    asm("{\n\t.reg .b16 lo, hi;\n\t"
        "cvt.rn.f16.f32 lo, %1;\n\t"
        "cvt.rn.f16.f32 hi, %2;\n\t"
        "mov.b32 %0, {lo, hi};\n\t}"
        : "=r"(r) : "f"(x), "f"(y));
    return r;
}

__device__ __forceinline__ void cp_async16(uint32_t dst, const void* src) {
    asm volatile("cp.async.cg.shared.global [%0], [%1], 16;" :: "r"(dst), "l"(src));
}
__device__ __forceinline__ void cp_commit() {
    asm volatile("cp.async.commit_group;");
}
template <int N>
__device__ __forceinline__ void cp_wait() {
    asm volatile("cp.async.wait_group %0;" :: "n"(N));
}

// ---------------------------------------------------------------------------
// Merged projection GEMMs: one launch, blockIdx.z in {0:q, 1:k, 2:v, 3:gate}
// C[m, n] = sum_c X[m, c] * W[n, c], tile M=128 x N=64, K-chunks of 64.
// Software-pipelined: LDGs for chunk k+1 in flight during mma of chunk k.
// ---------------------------------------------------------------------------
__global__ void __launch_bounds__(256) proj_all(const float* __restrict__ q_x,
                                                const float* __restrict__ k_x,
                                                const float* __restrict__ v_x,
                                                const float* __restrict__ wq,
                                                const float* __restrict__ wk,
                                                const float* __restrict__ wv,
                                                const float* __restrict__ wg,
                                                const float* __restrict__ bg) {
    __shared__ __half As[128 * LDQ];
    __shared__ __half Bs[64 * LDQ];

    const int z = blockIdx.z;
    const float* A = (z == 1) ? k_x : (z == 2) ? v_x : q_x;
    const float* B = (z == 0) ? wq : (z == 1) ? wk : (z == 2) ? wv : wg;

    const int m0 = blockIdx.y * 128, n0 = blockIdx.x * 64;
    const int tid = threadIdx.x;
    const int warp = tid >> 5;
    const int lane = tid & 31;
    const int g = lane >> 2, t = lane & 3;

    const int a_row = 16 * warp + (lane & 15);
    const int a_ch  = (lane >> 4) * 8;
    const int b_row = ((lane >> 4) & 1) * 8 + (lane & 7);
    const int b_ch  = ((lane >> 3) & 1) * 8;

    const int srow = tid >> 4;
    const int sc4  = (tid & 15) * 4;

    float acc[8][4] = {};
    float4 ar[8], br[4];

#pragma unroll
    for (int i = 0; i < 8; i++)
        ar[i] = *(const float4*)(A + (size_t)(m0 + srow + 16 * i) * CDIM + sc4);
#pragma unroll
    for (int i = 0; i < 4; i++)
        br[i] = *(const float4*)(B + (size_t)(n0 + srow + 16 * i) * CDIM + sc4);

    for (int k0 = 0; k0 < CDIM; k0 += 64) {
#pragma unroll
        for (int i = 0; i < 8; i++) {
            uint2 p;
            p.x = pack_f16x2(ar[i].x, ar[i].y);
            p.y = pack_f16x2(ar[i].z, ar[i].w);
            *(uint2*)(As + (srow + 16 * i) * LDQ + sc4) = p;
        }
#pragma unroll
        for (int i = 0; i < 4; i++) {
            uint2 p;
            p.x = pack_f16x2(br[i].x, br[i].y);
            p.y = pack_f16x2(br[i].z, br[i].w);
            *(uint2*)(Bs + (srow + 16 * i) * LDQ + sc4) = p;
        }
        __syncthreads();

        if (k0 + 64 < CDIM) {
#pragma unroll
            for (int i = 0; i < 8; i++)
                ar[i] = *(const float4*)(A + (size_t)(m0 + srow + 16 * i) * CDIM + k0 + 64 + sc4);
#pragma unroll
            for (int i = 0; i < 4; i++)
                br[i] = *(const float4*)(B + (size_t)(n0 + srow + 16 * i) * CDIM + k0 + 64 + sc4);
        }

#pragma unroll
        for (int kk = 0; kk < 4; kk++) {
            uint32_t qa[4];
            ldsm_x4(qa[0], qa[1], qa[2], qa[3],
                    smaddr(As + a_row * LDQ + 16 * kk + a_ch));
#pragma unroll
            for (int jp = 0; jp < 4; jp++) {
                uint32_t b0, b1, b2, b3;
                ldsm_x4(b0, b1, b2, b3,
                        smaddr(Bs + (16 * jp + b_row) * LDQ + 16 * kk + b_ch));
                mma16816(acc[2 * jp],     qa, b0, b1);
                mma16816(acc[2 * jp + 1], qa, b2, b3);
            }
        }
        __syncthreads();
    }

#pragma unroll
    for (int r = 0; r < 2; r++) {
#pragma unroll
        for (int j = 0; j < 8; j++) {
            const int row = m0 + 16 * warp + g + 8 * r;
            const int col = n0 + 8 * j + 2 * t;
            float x = acc[j][2 * r], y = acc[j][2 * r + 1];
            if (z == 0) {
                *(uint32_t*)(g_qh + (size_t)row * HD + col) = pack_f16x2(x * 0.125f, y * 0.125f);
            } else if (z == 1) {
                *(uint32_t*)(g_kh + (size_t)row * HD + col) = pack_f16x2(x, y);
            } else if (z == 2) {
                *(uint32_t*)(g_vh + (size_t)row * HD + col) = pack_f16x2(x, y);
            } else {
                float2 bv = *(const float2*)(bg + col);
                float2 ov;
                ov.x = 1.0f / (1.0f + __expf(-(x + bv.x)));
                ov.y = 1.0f / (1.0f + __expf(-(y + bv.y)));
                *(float2*)(g_g + (size_t)row * HD + col) = ov;
            }
        }
    }
}

// ---------------------------------------------------------------------------
// Output GEMM: out[m, n] = sum_j g_oh[m, j] * wo[n, j] + bo[n]   (A fp16)
// Register-staged pipeline over 8 K-chunks (A uint4 raw, B fp32->f16).
// ---------------------------------------------------------------------------
__global__ void __launch_bounds__(256) out_gemm(const float* __restrict__ W,
                                                const float* __restrict__ bvec,
                                                float* __restrict__ outp) {
    __shared__ __half As[128 * LDQ];
    __shared__ __half Bs[64 * LDQ];

    const int m0 = blockIdx.y * 128, n0 = blockIdx.x * 64;
    const int tid = threadIdx.x;
    const int warp = tid >> 5;
    const int lane = tid & 31;
    const int g = lane >> 2, t = lane & 3;

    const int a_row = 16 * warp + (lane & 15);
    const int a_ch  = (lane >> 4) * 8;
    const int b_row = ((lane >> 4) & 1) * 8 + (lane & 7);
    const int b_ch  = ((lane >> 3) & 1) * 8;

    const int arow_s = tid >> 3;
    const int ac8    = (tid & 7) * 8;
    const int brow_s = tid >> 4;
    const int bc4    = (tid & 15) * 4;

    float acc[8][4] = {};
    uint4  ar[4];
    float4 br[4];

#pragma unroll
    for (int i = 0; i < 4; i++)
        ar[i] = *(const uint4*)(g_oh + (size_t)(m0 + arow_s + 32 * i) * HD + ac8);
#pragma unroll
    for (int i = 0; i < 4; i++)
        br[i] = *(const float4*)(W + (size_t)(n0 + brow_s + 16 * i) * HD + bc4);

    for (int k0 = 0; k0 < HD; k0 += 64) {
#pragma unroll
        for (int i = 0; i < 4; i++)
            *(uint4*)(As + (arow_s + 32 * i) * LDQ + ac8) = ar[i];
#pragma unroll
        for (int i = 0; i < 4; i++) {
            uint2 p;
            p.x = pack_f16x2(br[i].x, br[i].y);
            p.y = pack_f16x2(br[i].z, br[i].w);
            *(uint2*)(Bs + (brow_s + 16 * i) * LDQ + bc4) = p;
        }
        __syncthreads();

        if (k0 + 64 < HD) {
#pragma unroll
            for (int i = 0; i < 4; i++)
                ar[i] = *(const uint4*)(g_oh + (size_t)(m0 + arow_s + 32 * i) * HD + k0 + 64 + ac8);
#pragma unroll
            for (int i = 0; i < 4; i++)
                br[i] = *(const float4*)(W + (size_t)(n0 + brow_s + 16 * i) * HD + k0 + 64 + bc4);
        }

#pragma unroll
        for (int kk = 0; kk < 4; kk++) {
            uint32_t qa[4];
            ldsm_x4(qa[0], qa[1], qa[2], qa[3],
                    smaddr(As + a_row * LDQ + 16 * kk + a_ch));
#pragma unroll
            for (int jp = 0; jp < 4; jp++) {
                uint32_t b0, b1, b2, b3;
                ldsm_x4(b0, b1, b2, b3,
                        smaddr(Bs + (16 * jp + b_row) * LDQ + 16 * kk + b_ch));
                mma16816(acc[2 * jp],     qa, b0, b1);
                mma16816(acc[2 * jp + 1], qa, b2, b3);
            }
        }
        __syncthreads();
    }

#pragma unroll
    for (int r = 0; r < 2; r++) {
#pragma unroll
        for (int j = 0; j < 8; j++) {
            const int row = m0 + 16 * warp + g + 8 * r;
            const int col = n0 + 8 * j + 2 * t;
            float2 bv = *(const float2*)(bvec + col);
            float2 ov;
            ov.x = acc[j][2 * r]     + bv.x;
            ov.y = acc[j][2 * r + 1] + bv.y;
            *(float2*)(outp + (size_t)row * CDIM + col) = ov;
        }
    }
}

// ---------------------------------------------------------------------------
// Split-KV flash attention. Grid (32 q-tiles, 8 heads, 4 kv-parts) = 1024
// equal blocks. No-max softmax is linear over kv, so partials (O_unnorm f16,
// rowsum f32) just add in the combine kernel. QK f16-accum, PV f32-accum,
// fp32 bias + softmax. Q fragments hoisted.
// ---------------------------------------------------------------------------
__global__ void __launch_bounds__(256, 2) attn_kernel(const float* __restrict__ bias) {
    extern __shared__ __half sm[];
    __half* Qs = sm;                         // [128][LDQ]
    __half* Ks = Qs + 128 * LDQ;             // [2][64][LDQ]
    __half* Vs = Ks + 2 * 64 * LDQ;          // [2][64][LDQ]

    const int h    = blockIdx.y;
    const int q0   = blockIdx.x * 128;
    const int part = blockIdx.z;
    const int kvb  = part * (NSEQ / KVPARTS);

    const int tid = threadIdx.x;
    const int warp = tid >> 5;
    const int lane = tid & 31;
    const int g  = lane >> 2;
    const int t  = lane & 3;

    for (int u = tid; u < 1024; u += 256) {
        const int row = u >> 3;
        const int c8  = (u & 7) * 8;
        *(uint4*)(Qs + row * LDQ + c8) =
            *(const uint4*)(g_qh + (size_t)(q0 + row) * HD + h * DDIM + c8);
    }

    float o[8][4];
#pragma unroll
    for (int j = 0; j < 8; j++)
#pragma unroll
        for (int e = 0; e < 4; e++) o[j][e] = 0.0f;
    float lrun[2] = {0.0f, 0.0f};

    const int a_row = 16 * warp + (lane & 15);
    const int a_ch  = (lane >> 4) * 8;
    const int b_row = ((lane >> 4) & 1) * 8 + (lane & 7);
    const int b_ch  = ((lane >> 3) & 1) * 8;
    const int v_row = ((lane >> 3) & 1) * 8 + (lane & 7);
    const int v_ch  = ((lane >> 4) & 1) * 8;

    const int cp_row = tid >> 2;
    const int cp_c8  = (tid & 3) * 16;

    // Prologue: K/V tile 0 of this part
    {
        const __half* kp = g_kh + (size_t)(kvb + cp_row) * HD + h * DDIM + cp_c8;
        const __half* vp = g_vh + (size_t)(kvb + cp_row) * HD + h * DDIM + cp_c8;
        uint32_t kd = smaddr(Ks + cp_row * LDQ + cp_c8);
        uint32_t vd = smaddr(Vs + cp_row * LDQ + cp_c8);
        cp_async16(kd, kp);           cp_async16(kd + 16, kp + 8);
        cp_async16(vd, vp);           cp_async16(vd + 16, vp + 8);
        cp_commit();
    }

    // Hoist Q fragments (Qs stable once loaded)
    __syncthreads();
    uint32_t qa[4][4];
#pragma unroll
    for (int kk = 0; kk < 4; kk++)
        ldsm_x4(qa[kk][0], qa[kk][1], qa[kk][2], qa[kk][3],
                smaddr(Qs + a_row * LDQ + 16 * kk + a_ch));

    const float* bias_base = bias + (size_t)(q0 + 16 * warp + g) * NSEQ;

    for (int kt = 0; kt < NTP; kt++) {
        const int buf = kt & 1;
        __half* Kb = Ks + buf * 64 * LDQ;
        __half* Vb = Vs + buf * 64 * LDQ;

        __syncthreads();

        // Prefetch tile kt+1
        if (kt + 1 < NTP) {
            const int k0n = kvb + (kt + 1) * 64;
            const __half* kp = g_kh + (size_t)(k0n + cp_row) * HD + h * DDIM + cp_c8;
            const __half* vp = g_vh + (size_t)(k0n + cp_row) * HD + h * DDIM + cp_c8;
            uint32_t kd = smaddr(Ks + (buf ^ 1) * 64 * LDQ + cp_row * LDQ + cp_c8);
            uint32_t vd = smaddr(Vs + (buf ^ 1) * 64 * LDQ + cp_row * LDQ + cp_c8);
            cp_async16(kd, kp);       cp_async16(kd + 16, kp + 8);
            cp_async16(vd, vp);       cp_async16(vd + 16, vp + 8);
        }
        cp_commit();

        // Bias loads for tile kt (fp32; LDGs in flight during wait + mma)
        const int k0 = kvb + kt * 64;
        float2 bb0[8], bb1[8];
#pragma unroll
        for (int j = 0; j < 8; j++) {
            const int col = k0 + 8 * j + 2 * t;
            bb0[j] = *(const float2*)(bias_base + col);
            bb1[j] = *(const float2*)(bias_base + (size_t)8 * NSEQ + col);
        }

        cp_wait<1>();
        __syncthreads();

        // S = Q K^T  (f16 accumulate, zero-init)
        uint32_t sf[8][2];
#pragma unroll
        for (int j = 0; j < 8; j++) { sf[j][0] = 0u; sf[j][1] = 0u; }

#pragma unroll
        for (int kk = 0; kk < 4; kk++) {
#pragma unroll
            for (int jp = 0; jp < 4; jp++) {
                uint32_t b0, b1, b2, b3;
                ldsm_x4(b0, b1, b2, b3,
                        smaddr(Kb + (16 * jp + b_row) * LDQ + 16 * kk + b_ch));
                mma16816_h(sf[2 * jp],     qa[kk], b0, b1);
                mma16816_h(sf[2 * jp + 1], qa[kk], b2, b3);
            }
        }

        // Softmax without max-subtraction; pack P into A-fragments
        uint32_t pa[4][4];
#pragma unroll
        for (int j = 0; j < 8; j++) {
            float2 lo = __half22float2(*(const __half2*)&sf[j][0]);
            float2 hi = __half22float2(*(const __half2*)&sf[j][1]);
            const float p00 = __expf(lo.x + bb0[j].x);
            const float p01 = __expf(lo.y + bb0[j].y);
            const float p10 = __expf(hi.x + bb1[j].x);
            const float p11 = __expf(hi.y + bb1[j].y);
            lrun[0] += p00 + p01;
            lrun[1] += p10 + p11;
            const int m = j >> 1;
            const int hl = j & 1;
            pa[m][2 * hl]     = pack_f16x2(p00, p01);
            pa[m][2 * hl + 1] = pack_f16x2(p10, p11);
        }

        // O += P V (f32 accumulate)
#pragma unroll
        for (int m = 0; m < 4; m++) {
#pragma unroll
            for (int jp = 0; jp < 4; jp++) {
                uint32_t b0, b1, b2, b3;
                ldsm_x4_t(b0, b1, b2, b3,
                          smaddr(Vb + (16 * m + v_row) * LDQ + 16 * jp + v_ch));
                mma16816(o[2 * jp],     pa[m], b0, b1);
                mma16816(o[2 * jp + 1], pa[m], b2, b3);
            }
        }
    }

    // Reduce row sums across the 4 t-lanes
#pragma unroll
    for (int r = 0; r < 2; r++) {
        lrun[r] += __shfl_xor_sync(0xffffffffu, lrun[r], 1);
        lrun[r] += __shfl_xor_sync(0xffffffffu, lrun[r], 2);
    }

    // Epilogue: write unnormalized f16 partials + row sums for this part
    __half* opart = g_opart[part];
#pragma unroll
    for (int r = 0; r < 2; r++) {
        const int row = q0 + 16 * warp + g + 8 * r;
        if (t == 0)
            g_ls[part][h * NSEQ + row] = lrun[r];
        const size_t rb = (size_t)row * HD + h * DDIM;
#pragma unroll
        for (int j = 0; j < 8; j++) {
            const int col = 8 * j + 2 * t;
            *(uint32_t*)(opart + rb + col) = pack_f16x2(o[j][2 * r], o[j][2 * r + 1]);
        }
    }
}

// ---------------------------------------------------------------------------
// Combine: sum the 4 f16 kv-part partials, normalize, gate, store fp16 g_oh.
// ---------------------------------------------------------------------------
__global__ void __launch_bounds__(256) combine_kernel() {
    const size_t idx = ((size_t)blockIdx.x * 256 + threadIdx.x) * 4;
    const int row = (int)(idx / HD);
    const int col = (int)(idx % HD);
    const int h   = col / DDIM;

    float sx = 0.0f, sy = 0.0f, sz = 0.0f, sw = 0.0f;
#pragma unroll
    for (int p = 0; p < KVPARTS; p++) {
        uint2 raw = *(const uint2*)(g_opart[p] + idx);
        float2 a = __half22float2(*(const __half2*)&raw.x);
        float2 b = __half22float2(*(const __half2*)&raw.y);
        sx += a.x; sy += a.y; sz += b.x; sw += b.y;
    }

    const int li = h * NSEQ + row;
    float l = 0.0f;
#pragma unroll
    for (int p = 0; p < KVPARTS; p++) l += g_ls[p][li];
    const float inv = 1.0f / l;

    float4 gv = *(const float4*)(g_g + idx);
    uint2 pk;
    pk.x = pack_f16x2(sx * inv * gv.x, sy * inv * gv.y);
    pk.y = pack_f16x2(sz * inv * gv.z, sw * inv * gv.w);
    *(uint2*)(g_oh + idx) = pk;
}

// ---------------------------------------------------------------------------
extern "C" void kernel_launch(void* const* d_in, const int* in_sizes, int n_in,
                              void* d_out, int out_size) {
    const float* q_x  = (const float*)d_in[0];
    const float* k_x  = (const float*)d_in[1];
    const float* v_x  = (const float*)d_in[2];
    const float* bias = (const float*)d_in[3];
    const float* wq   = (const float*)d_in[4];
    const float* wk   = (const float*)d_in[5];
    const float* wv   = (const float*)d_in[6];
    const float* wg   = (const float*)d_in[7];
    const float* bg   = (const float*)d_in[8];
    const float* wo   = (const float*)d_in[9];
    const float* bo   = (const float*)d_in[10];
    float* out = (float*)d_out;

    proj_all<<<dim3(HD / 64, NSEQ / 128, 4), 256>>>(q_x, k_x, v_x, wq, wk, wv, wg, bg);

    const size_t smem = (size_t)(128 + 4 * 64) * LDQ * sizeof(__half);  // 55296 B
    cudaFuncSetAttribute(attn_kernel, cudaFuncAttributeMaxDynamicSharedMemorySize, (int)smem);
    attn_kernel<<<dim3(NSEQ / 128, HEADS, KVPARTS), 256, smem>>>(bias);

    combine_kernel<<<(NSEQ * HD) / 1024, 256>>>();

    out_gemm<<<dim3(CDIM / 64, NSEQ / 128), 256>>>(wo, bo, out);
}